// round 16
// baseline (speedup 1.0000x reference)
#include <cuda_runtime.h>
#include <cuda_fp16.h>
#include <cstdint>

typedef unsigned long long u64;
typedef long long           i64;

// ---------------------------------------------------------------------------
#define B_   256
#define T_   100
#define I_   2048
#define H_   2048
#define M_   (B_ * T_)      // 25600

#define BM   64
#define BN   128
#define MT   (M_ / BM)      // 400
#define NT   (H_ / BN)      // 16
#define NCHUNK (I_ / 64)    // 32 K-chunks of 64 fp16 elements (128 bytes/row)

#define NSLICE 3            // base-512 digits: 3 slices per operand
#define PLANE_A 8192        // 64 rows x 128 B
#define PLANE_B 16384       // 128 rows x 128 B
#define OFF_B   (NSLICE * PLANE_A)               // 24576
#define STAGE   (OFF_B + NSLICE * PLANE_B)       // 73728
#define NSTAGES 3
#define DSMEM   (NSTAGES * STAGE)                // 221184 (< 227 KB cap)

#define NTHR 256            // 8 warps: 2 M-groups x 4 N-groups, warp tile m32n32

// Static device scratch (no allocations). Digits stored as fp16 bit patterns.
__device__ __align__(16) unsigned short g_Xs[(i64)NSLICE * M_ * I_];   // 300 MiB
__device__ __align__(16) unsigned short g_Ws[(i64)NSLICE * H_ * I_];   // 24 MiB
__device__ float g_sxf[M_];
__device__ float g_swf[H_];
__device__ float g_proj[(size_t)M_ * H_];                              // 200 MiB

// ---------------------------------------------------------------------------
// helpers (family-common PTX only)
// ---------------------------------------------------------------------------
__device__ __forceinline__ uint32_t smem_u32(const void* p) {
    uint32_t a;
    asm("{ .reg .u64 t; cvta.to.shared.u64 t, %1; cvt.u32.u64 %0, t; }" : "=r"(a) : "l"(p));
    return a;
}
__device__ __forceinline__ uint32_t sw128(uint32_t o) { return o ^ ((o >> 3) & 0x70); }

__device__ __forceinline__ void ldsm4(uint32_t& r0, uint32_t& r1, uint32_t& r2, uint32_t& r3,
                                      uint32_t a) {
    asm volatile("ldmatrix.sync.aligned.m8n8.x4.shared.b16 {%0,%1,%2,%3}, [%4];"
                 : "=r"(r0), "=r"(r1), "=r"(r2), "=r"(r3) : "r"(a));
}
__device__ __forceinline__ void cpa16(uint32_t d, const void* s) {
    asm volatile("cp.async.cg.shared.global [%0], [%1], 16;" :: "r"(d), "l"(s));
}
#define CP_COMMIT() asm volatile("cp.async.commit_group;")
#define CP_WAIT1()  asm volatile("cp.async.wait_group 1;")

// fp16 HMMA, fp32 accumulate (exact: integer digit products, |S| <= 2^24)
#define MMA(d, a, b) \
    asm volatile("mma.sync.aligned.m16n8k16.row.col.f32.f16.f16.f32 " \
                 "{%0,%1,%2,%3}, {%4,%5,%6,%7}, {%8,%9}, {%0,%1,%2,%3};" \
                 : "+f"((d)[0]), "+f"((d)[1]), "+f"((d)[2]), "+f"((d)[3]) \
                 : "r"((a)[0]), "r"((a)[1]), "r"((a)[2]), "r"((a)[3]), \
                   "r"((b)[0]), "r"((b)[1]))

// ---------------------------------------------------------------------------
// Split: per-row power-of-2 scale 2^e (> max|x|), 3 SIGNED base-512 digits:
// u = d0/2^8 + d1/2^17 + d2/2^26 + tail (|tail| <= 2^-27), |d_i| <= 256,
// all peel steps exact fp32. Digits exact in fp16.
// *** NUMERICS FROZEN: identical per-element math to R14/R15 (4.1e-7). ***
// Vectorized: float4 reads, ushort4 digit stores (pure IO change).
// ---------------------------------------------------------------------------
__global__ __launch_bounds__(256)
void split_kernel(const float* __restrict__ src, unsigned short* __restrict__ dst,
                  float* __restrict__ scl, i64 sstride)
{
    __shared__ float smax[256];
    __shared__ float s_inv;

    const int r = blockIdx.x;
    const int tid = threadIdx.x;
    const float* row = src + (size_t)r * I_;

    float mx = 0.0f;
    #pragma unroll
    for (int it = 0; it < I_ / 1024; it++) {
        float4 x = *(const float4*)(row + (tid + it * 256) * 4);
        mx = fmaxf(mx, fmaxf(fmaxf(fabsf(x.x), fabsf(x.y)),
                             fmaxf(fabsf(x.z), fabsf(x.w))));
    }
    smax[tid] = mx;
    __syncthreads();
    for (int s = 128; s > 0; s >>= 1) {
        if (tid < s) smax[tid] = fmaxf(smax[tid], smax[tid + s]);
        __syncthreads();
    }
    if (tid == 0) {
        int e = 0;
        if (smax[0] > 0.0f) frexpf(smax[0], &e);   // max = f*2^e, f in [0.5,1)
        s_inv = ldexpf(1.0f, -e);                  // |u| < 1
        scl[r] = ldexpf(1.0f, e - 17);             // pair scale: 2^(ex+ew-34)
    }
    __syncthreads();
    const float sinv = s_inv;

    #pragma unroll
    for (int it = 0; it < I_ / 1024; it++) {
        int k0 = (tid + it * 256) * 4;
        float4 x = *(const float4*)(row + k0);
        float xs[4] = { x.x, x.y, x.z, x.w };
        ushort4 o0, o1, o2;
        unsigned short* p0 = &o0.x;
        unsigned short* p1 = &o1.x;
        unsigned short* p2 = &o2.x;
        #pragma unroll
        for (int j = 0; j < 4; j++) {
            float u  = xs[j] * sinv;                   // exact, |u| < 1
            float v0 = u * 256.0f;                     // exact, |v0| < 256
            float d0 = rintf(v0);  float r0 = v0 - d0; // exact, |d0|<=256
            float v1 = r0 * 512.0f;
            float d1 = rintf(v1);  float r1 = v1 - d1; // |d1|<=256
            float d2 = rintf(r1 * 512.0f);             // |d2|<=256, tail dropped
            p0[j] = __half_as_ushort(__float2half_rn(d0));
            p1[j] = __half_as_ushort(__float2half_rn(d1));
            p2[j] = __half_as_ushort(__float2half_rn(d2));
        }
        i64 base = (i64)r * I_ + k0;
        *(ushort4*)(dst + 0 * sstride + base) = o0;
        *(ushort4*)(dst + 1 * sstride + base) = o1;
        *(ushort4*)(dst + 2 * sstride + base) = o2;
    }
}

// ---------------------------------------------------------------------------
// GEMM: fp16 HMMA, 6 digit pairs (i+j<=2), THREE shared-s fp32 accumulator
// sets. Staggered folds (same cadence as R15, bit-identical P), but DEFERRED
// one chunk: chunk c's folds execute at the top of iteration c+1, after the
// cp.async wait + barrier (~100+ cyc after the last mma wrote D), so F2I never
// stalls on mma writeback latency. Bounds unchanged:
//   s=2: fold per chunk (3*64*2^16 = 2^23.58)
//   s=1: per 2 chunks   (2*128*2^16 = 2^24)
//   s=0: per 4 chunks   (1*256*2^16 = 2^24)
// CTA 64x128, 8 warps (2M x 4N), warp tile m32n32, 3-stage cp.async pipeline.
// ---------------------------------------------------------------------------
__global__ __launch_bounds__(NTHR, 1)
void lif_gemm_hmma_kernel(const float* __restrict__ bias, float* __restrict__ proj)
{
    extern __shared__ int8_t smem[];
    const uint32_t sb = smem_u32(smem);
    const int tid  = threadIdx.x;
    const int lane = tid & 31;
    const int wid  = tid >> 5;
    const int wm   = wid >> 2;    // 0..1 -> M group (32 rows)
    const int wn   = wid & 3;     // 0..3 -> N group (32 cols)
    const int bx = blockIdx.x;    // N tile (128)
    const int by = blockIdx.y;    // M tile (64)

    const int q  = lane >> 3;
    const int l7 = lane & 7;

    float D[3][8][4];   // [s][tile = mt*4+nt][e]
    i64   P[8][4];
    #pragma unroll
    for (int s = 0; s < 3; s++)
        #pragma unroll
        for (int t = 0; t < 8; t++)
            #pragma unroll
            for (int e = 0; e < 4; e++) D[s][t][e] = 0.0f;
    #pragma unroll
    for (int t = 0; t < 8; t++)
        #pragma unroll
        for (int e = 0; e < 4; e++) P[t][e] = 0ll;

// chunk = A 24KB (3 planes x 64 rows) + B 48KB (3 planes x 128 rows) = 4608
// vec16; 18 per thread at 256 thr. v 0..5 -> A, v 6..17 -> B.
#define LOAD_CHUNK(c) do {                                                        \
    uint32_t stg = sb + ((c) % NSTAGES) * STAGE;                                  \
    _Pragma("unroll")                                                             \
    for (int v = 0; v < 6; v++) {                                                 \
        int id = v * NTHR + tid;                                                  \
        int sl = id >> 9;                                                         \
        int idx = id & 511;                                                       \
        int row = idx >> 3, x = idx & 7;                                          \
        uint32_t dst = stg + sl * PLANE_A + sw128((uint32_t)(row * 128 + x * 16));\
        cpa16(dst, g_Xs + (i64)sl * M_ * I_ + (i64)(by * BM + row) * I_           \
                       + (c) * 64 + x * 8);                                       \
    }                                                                             \
    _Pragma("unroll")                                                             \
    for (int v = 0; v < 12; v++) {                                                \
        int id = v * NTHR + tid;                                                  \
        int sl = id >> 10;                                                        \
        int idx = id & 1023;                                                      \
        int row = idx >> 3, x = idx & 7;                                          \
        uint32_t dst = stg + OFF_B + sl * PLANE_B                                 \
                     + sw128((uint32_t)(row * 128 + x * 16));                     \
        cpa16(dst, g_Ws + (i64)sl * H_ * I_ + (i64)(bx * BN + row) * I_           \
                       + (c) * 64 + x * 8);                                       \
    }                                                                             \
    CP_COMMIT();                                                                  \
} while (0)

// pair (i,j) -> accumulator set s=i+j; 8 m16n8 tile-mma per pair (m32 x n32)
#define PP(i, j, s) {                                                             \
    _Pragma("unroll")                                                             \
    for (int mt = 0; mt < 2; mt++)                                                \
        _Pragma("unroll")                                                         \
        for (int nt = 0; nt < 4; nt++)                                            \
            MMA(D[s][mt * 4 + nt], A[i][mt], Bt[j][nt]);                          \
}

#define COMPUTE_CHUNK(c) do {                                                     \
    uint32_t stg = sb + ((c) % NSTAGES) * STAGE;                                  \
    _Pragma("unroll")                                                             \
    for (int ks = 0; ks < 4; ks++) {                                              \
        uint32_t A[NSLICE][2][4];                                                 \
        _Pragma("unroll")                                                         \
        for (int sl = 0; sl < NSLICE; sl++) {                                     \
            _Pragma("unroll")                                                     \
            for (int mt = 0; mt < 2; mt++) {                                      \
                int row = wm * 32 + mt * 16 + ((q & 1) << 3) + l7;                \
                uint32_t ad = stg + sl * PLANE_A                                  \
                            + sw128((uint32_t)(row * 128 + ks * 32 + (q >> 1) * 16)); \
                ldsm4(A[sl][mt][0], A[sl][mt][1], A[sl][mt][2], A[sl][mt][3], ad);\
            }                                                                     \
        }                                                                         \
        uint32_t Bt[NSLICE][4][2];                                                \
        _Pragma("unroll")                                                         \
        for (int sl = 0; sl < NSLICE; sl++) {                                     \
            _Pragma("unroll")                                                     \
            for (int g = 0; g < 2; g++) {                                         \
                int n = wn * 32 + g * 16 + ((q & 1) << 3) + l7;                   \
                uint32_t bd = stg + OFF_B + sl * PLANE_B                          \
                            + sw128((uint32_t)(n * 128 + ks * 32 + (q >> 1) * 16)); \
                uint32_t r0, r1, r2, r3;                                          \
                ldsm4(r0, r1, r2, r3, bd);                                        \
                Bt[sl][2 * g][0] = r0;     Bt[sl][2 * g][1] = r2;                 \
                Bt[sl][2 * g + 1][0] = r1; Bt[sl][2 * g + 1][1] = r3;             \
            }                                                                     \
        }                                                                         \
        PP(0,0,0) PP(0,1,1) PP(0,2,2) PP(1,0,1) PP(1,1,2) PP(2,0,2)               \
    }                                                                             \
} while (0)

// Fold ONE accumulator set into P (shift = 9*(2-s)). Integer-exact.
#define FOLD_S(s, shift) do {                                                     \
    _Pragma("unroll")                                                             \
    for (int t = 0; t < 8; t++) {                                                 \
        _Pragma("unroll")                                                         \
        for (int e = 0; e < 4; e++) {                                             \
            P[t][e] += ((i64)(int)D[s][t][e] << (shift));                         \
            D[s][t][e] = 0.0f;                                                    \
        }                                                                         \
    }                                                                             \
} while (0)

    LOAD_CHUNK(0);
    LOAD_CHUNK(1);
    #pragma unroll 1
    for (int c = 0; c < NCHUNK; c++) {
        CP_WAIT1();            // chunk c resident (<=1 group pending)
        __syncthreads();       // all warps see chunk c; compute(c-1) done
        if (c + 2 < NCHUNK) LOAD_CHUNK(c + 2);   // overwrites stage (c-1): safe
        // Deferred folds for chunk c-1 (scoreboard long drained -> no stall).
        if (c > 0) {
            FOLD_S(2, 0);
            if (((c - 1) & 1) == 1) FOLD_S(1, 9);
            if (((c - 1) & 3) == 3) FOLD_S(0, 18);
        }
        COMPUTE_CHUNK(c);
    }
    // Flush folds for the last chunk (c = 31: odd, 31&3 == 3)
    FOLD_S(2, 0);
    FOLD_S(1, 9);
    FOLD_S(0, 18);

    // ---- epilogue: proj = P * 2^(ex+ew-34) + bias, one rounding ----
    #pragma unroll
    for (int mt = 0; mt < 2; mt++) {
        #pragma unroll
        for (int half = 0; half < 2; half++) {
            int m = by * BM + wm * 32 + mt * 16 + 8 * half + (lane >> 2);
            double sx = (double)g_sxf[m];            // 2^(ex-17)
            float* orow = proj + (size_t)m * H_ + bx * BN + wn * 32 + 2 * (lane & 3);
            #pragma unroll
            for (int nt = 0; nt < 4; nt++) {
                int t = mt * 4 + nt;
                float v[2];
                #pragma unroll
                for (int dj = 0; dj < 2; dj++) {
                    int h = bx * BN + wn * 32 + nt * 8 + 2 * (lane & 3) + dj;
                    int e = 2 * half + dj;
                    double sc = sx * (double)g_swf[h];   // 2^(ex+ew-34), exact
                    v[dj] = (float)((double)P[t][e] * sc + (double)bias[h]);
                }
                *(float2*)(orow + nt * 8) = make_float2(v[0], v[1]);
            }
        }
    }
#undef LOAD_CHUNK
#undef COMPUTE_CHUNK
#undef PP
#undef FOLD_S
}

// ---------------------------------------------------------------------------
// LIF scan: 4 consecutive h per thread, float4 IO (per-element math unchanged
// -> bit-identical). 131072 threads.
// ---------------------------------------------------------------------------
__global__ __launch_bounds__(256)
void lif_scan_kernel(const float* __restrict__ proj, float* __restrict__ out)
{
    int idx = blockIdx.x * blockDim.x + threadIdx.x;  // 0 .. B_*H_/4 - 1
    if (idx >= B_ * (H_ / 4)) return;
    int b  = idx / (H_ / 4);
    int h4 = idx % (H_ / 4);

    const float4* pin  = (const float4*)(proj + (size_t)b * T_ * H_) + h4;
    float4*       pout = (float4*)(out + (size_t)b * T_ * H_) + h4;

    float hs0 = 0.0f, hs1 = 0.0f, hs2 = 0.0f, hs3 = 0.0f;

    #pragma unroll 4
    for (int t = 0; t < T_; t++) {
        float4 p = pin[(size_t)t * (H_ / 4)];
        float4 sp;
        hs0 = __fadd_rn(__fmul_rn(0.9f, hs0), p.x);
        sp.x = (hs0 >= 1.0f) ? 1.0f : 0.0f;
        hs0 = __fmul_rn(hs0, __fsub_rn(1.0f, sp.x));
        hs1 = __fadd_rn(__fmul_rn(0.9f, hs1), p.y);
        sp.y = (hs1 >= 1.0f) ? 1.0f : 0.0f;
        hs1 = __fmul_rn(hs1, __fsub_rn(1.0f, sp.y));
        hs2 = __fadd_rn(__fmul_rn(0.9f, hs2), p.z);
        sp.z = (hs2 >= 1.0f) ? 1.0f : 0.0f;
        hs2 = __fmul_rn(hs2, __fsub_rn(1.0f, sp.z));
        hs3 = __fadd_rn(__fmul_rn(0.9f, hs3), p.w);
        sp.w = (hs3 >= 1.0f) ? 1.0f : 0.0f;
        hs3 = __fmul_rn(hs3, __fsub_rn(1.0f, sp.w));
        pout[(size_t)t * (H_ / 4)] = sp;
    }

    float4* pfin = (float4*)(out + (size_t)B_ * T_ * H_ + (size_t)b * H_) + h4;
    *pfin = make_float4(hs0, hs1, hs2, hs3);
}

// ---------------------------------------------------------------------------
extern "C" void kernel_launch(void* const* d_in, const int* in_sizes, int n_in,
                              void* d_out, int out_size)
{
    const float* X    = (const float*)d_in[0];
    const float* W    = (const float*)d_in[1];
    const float* bias = (const float*)d_in[2];
    float* out = (float*)d_out;

    unsigned short *Xs, *Ws;
    float *sxf, *swf, *proj;
    cudaGetSymbolAddress((void**)&Xs, g_Xs);
    cudaGetSymbolAddress((void**)&Ws, g_Ws);
    cudaGetSymbolAddress((void**)&sxf, g_sxf);
    cudaGetSymbolAddress((void**)&swf, g_swf);
    cudaGetSymbolAddress((void**)&proj, g_proj);

    cudaFuncSetAttribute(lif_gemm_hmma_kernel,
                         cudaFuncAttributeMaxDynamicSharedMemorySize, DSMEM);

    // signed base-512 digit splits (3 fp16 planes per operand) — FROZEN math
    split_kernel<<<M_, 256>>>(X, Xs, sxf, (i64)M_ * I_);
    split_kernel<<<H_, 256>>>(W, Ws, swf, (i64)H_ * I_);

    // fp16 HMMA GEMM, 6 pairs, deferred staggered folds (bit-identical output)
    dim3 ggrid(NT, MT);   // (16, 400): bx fastest -> X tiles shared in L2
    lif_gemm_hmma_kernel<<<ggrid, NTHR, DSMEM>>>(bias, proj);

    // LIF scan (float4, bit-identical arithmetic)
    lif_scan_kernel<<<(B_ * (H_ / 4) + 255) / 256, 256>>>(proj, out);
}

// round 17
// speedup vs baseline: 1.0187x; 1.0187x over previous
#include <cuda_runtime.h>
#include <cuda_fp16.h>
#include <cstdint>

typedef unsigned long long u64;
typedef long long           i64;

// ---------------------------------------------------------------------------
#define B_   256
#define T_   100
#define I_   2048
#define H_   2048
#define M_   (B_ * T_)      // 25600

#define BM   64
#define BN   128
#define MT   (M_ / BM)      // 400
#define NT   (H_ / BN)      // 16
#define NCHUNK (I_ / 64)    // 32 K-chunks of 64 fp16 elements (128 bytes/row)

#define NSLICE 3            // base-512 digits: 3 slices per operand
#define PLANE_A 8192        // 64 rows x 128 B
#define PLANE_B 16384       // 128 rows x 128 B
#define OFF_B   (NSLICE * PLANE_A)               // 24576
#define STAGE   (OFF_B + NSLICE * PLANE_B)       // 73728
#define NSTAGES 3
#define DSMEM   (NSTAGES * STAGE)                // 221184 (< 227 KB cap)

#define NTHR 256            // 8 warps: 2 M-groups x 4 N-groups, warp tile m32n32

// Static device scratch (no allocations). Digits stored as fp16 bit patterns.
__device__ __align__(16) unsigned short g_Xs[(i64)NSLICE * M_ * I_];   // 300 MiB
__device__ __align__(16) unsigned short g_Ws[(i64)NSLICE * H_ * I_];   // 24 MiB
__device__ float g_sxf[M_];
__device__ float g_swf[H_];
__device__ float g_proj[(size_t)M_ * H_];                              // 200 MiB

// ---------------------------------------------------------------------------
// helpers (family-common PTX only)
// ---------------------------------------------------------------------------
__device__ __forceinline__ uint32_t smem_u32(const void* p) {
    uint32_t a;
    asm("{ .reg .u64 t; cvta.to.shared.u64 t, %1; cvt.u32.u64 %0, t; }" : "=r"(a) : "l"(p));
    return a;
}
__device__ __forceinline__ uint32_t sw128(uint32_t o) { return o ^ ((o >> 3) & 0x70); }

__device__ __forceinline__ void ldsm4(uint32_t& r0, uint32_t& r1, uint32_t& r2, uint32_t& r3,
                                      uint32_t a) {
    asm volatile("ldmatrix.sync.aligned.m8n8.x4.shared.b16 {%0,%1,%2,%3}, [%4];"
                 : "=r"(r0), "=r"(r1), "=r"(r2), "=r"(r3) : "r"(a));
}
__device__ __forceinline__ void cpa16(uint32_t d, const void* s) {
    asm volatile("cp.async.cg.shared.global [%0], [%1], 16;" :: "r"(d), "l"(s));
}
#define CP_COMMIT() asm volatile("cp.async.commit_group;")
#define CP_WAIT1()  asm volatile("cp.async.wait_group 1;")

// fp16 HMMA, fp32 accumulate (exact: integer digit products, |S| <= 2^24)
#define MMA(d, a, b) \
    asm volatile("mma.sync.aligned.m16n8k16.row.col.f32.f16.f16.f32 " \
                 "{%0,%1,%2,%3}, {%4,%5,%6,%7}, {%8,%9}, {%0,%1,%2,%3};" \
                 : "+f"((d)[0]), "+f"((d)[1]), "+f"((d)[2]), "+f"((d)[3]) \
                 : "r"((a)[0]), "r"((a)[1]), "r"((a)[2]), "r"((a)[3]), \
                   "r"((b)[0]), "r"((b)[1]))

// ---------------------------------------------------------------------------
// Split: per-row power-of-2 scale 2^e (> max|x|), 3 SIGNED base-512 digits:
// u = d0/2^8 + d1/2^17 + d2/2^26 + tail (|tail| <= 2^-27), |d_i| <= 256,
// all peel steps exact fp32. Digits exact in fp16.
// *** NUMERICS FROZEN: identical per-element math to R14/R15 (4.1e-7). ***
// Vectorized IO: float4 reads, ushort4 digit stores (R16-measured win).
// ---------------------------------------------------------------------------
__global__ __launch_bounds__(256)
void split_kernel(const float* __restrict__ src, unsigned short* __restrict__ dst,
                  float* __restrict__ scl, i64 sstride)
{
    __shared__ float smax[256];
    __shared__ float s_inv;

    const int r = blockIdx.x;
    const int tid = threadIdx.x;
    const float* row = src + (size_t)r * I_;

    float mx = 0.0f;
    #pragma unroll
    for (int it = 0; it < I_ / 1024; it++) {
        float4 x = *(const float4*)(row + (tid + it * 256) * 4);
        mx = fmaxf(mx, fmaxf(fmaxf(fabsf(x.x), fabsf(x.y)),
                             fmaxf(fabsf(x.z), fabsf(x.w))));
    }
    smax[tid] = mx;
    __syncthreads();
    for (int s = 128; s > 0; s >>= 1) {
        if (tid < s) smax[tid] = fmaxf(smax[tid], smax[tid + s]);
        __syncthreads();
    }
    if (tid == 0) {
        int e = 0;
        if (smax[0] > 0.0f) frexpf(smax[0], &e);   // max = f*2^e, f in [0.5,1)
        s_inv = ldexpf(1.0f, -e);                  // |u| < 1
        scl[r] = ldexpf(1.0f, e - 17);             // pair scale: 2^(ex+ew-34)
    }
    __syncthreads();
    const float sinv = s_inv;

    #pragma unroll
    for (int it = 0; it < I_ / 1024; it++) {
        int k0 = (tid + it * 256) * 4;
        float4 x = *(const float4*)(row + k0);
        float xs[4] = { x.x, x.y, x.z, x.w };
        ushort4 o0, o1, o2;
        unsigned short* p0 = &o0.x;
        unsigned short* p1 = &o1.x;
        unsigned short* p2 = &o2.x;
        #pragma unroll
        for (int j = 0; j < 4; j++) {
            float u  = xs[j] * sinv;                   // exact, |u| < 1
            float v0 = u * 256.0f;                     // exact, |v0| < 256
            float d0 = rintf(v0);  float r0 = v0 - d0; // exact, |d0|<=256
            float v1 = r0 * 512.0f;
            float d1 = rintf(v1);  float r1 = v1 - d1; // |d1|<=256
            float d2 = rintf(r1 * 512.0f);             // |d2|<=256, tail dropped
            p0[j] = __half_as_ushort(__float2half_rn(d0));
            p1[j] = __half_as_ushort(__float2half_rn(d1));
            p2[j] = __half_as_ushort(__float2half_rn(d2));
        }
        i64 base = (i64)r * I_ + k0;
        *(ushort4*)(dst + 0 * sstride + base) = o0;
        *(ushort4*)(dst + 1 * sstride + base) = o1;
        *(ushort4*)(dst + 2 * sstride + base) = o2;
    }
}

// ---------------------------------------------------------------------------
// GEMM: fp16 HMMA, 6 digit pairs (i+j<=2), THREE shared-s fp32 accumulator
// sets. Staggered IMMEDIATE folds (R15 placement — R16 showed deferring them
// across the loop boundary extends D's register lifetimes and regresses):
//   s=2 (3 pairs): fold every chunk    (3*64*2^16  = 2^23.58 < 2^24)
//   s=1 (2 pairs): fold every 2 chunks (2*128*2^16 = 2^24, representable)
//   s=0 (1 pair) : fold every 4 chunks (1*256*2^16 = 2^24, representable)
// Integer sums order-independent -> P bit-identical.
// CTA 64x128, 8 warps (2M x 4N), warp tile m32n32, 3-stage cp.async pipeline.
// ---------------------------------------------------------------------------
__global__ __launch_bounds__(NTHR, 1)
void lif_gemm_hmma_kernel(const float* __restrict__ bias, float* __restrict__ proj)
{
    extern __shared__ int8_t smem[];
    const uint32_t sb = smem_u32(smem);
    const int tid  = threadIdx.x;
    const int lane = tid & 31;
    const int wid  = tid >> 5;
    const int wm   = wid >> 2;    // 0..1 -> M group (32 rows)
    const int wn   = wid & 3;     // 0..3 -> N group (32 cols)
    const int bx = blockIdx.x;    // N tile (128)
    const int by = blockIdx.y;    // M tile (64)

    const int q  = lane >> 3;
    const int l7 = lane & 7;

    float D[3][8][4];   // [s][tile = mt*4+nt][e]
    i64   P[8][4];
    #pragma unroll
    for (int s = 0; s < 3; s++)
        #pragma unroll
        for (int t = 0; t < 8; t++)
            #pragma unroll
            for (int e = 0; e < 4; e++) D[s][t][e] = 0.0f;
    #pragma unroll
    for (int t = 0; t < 8; t++)
        #pragma unroll
        for (int e = 0; e < 4; e++) P[t][e] = 0ll;

// chunk = A 24KB (3 planes x 64 rows) + B 48KB (3 planes x 128 rows) = 4608
// vec16; 18 per thread at 256 thr. v 0..5 -> A, v 6..17 -> B.
#define LOAD_CHUNK(c) do {                                                        \
    uint32_t stg = sb + ((c) % NSTAGES) * STAGE;                                  \
    _Pragma("unroll")                                                             \
    for (int v = 0; v < 6; v++) {                                                 \
        int id = v * NTHR + tid;                                                  \
        int sl = id >> 9;                                                         \
        int idx = id & 511;                                                       \
        int row = idx >> 3, x = idx & 7;                                          \
        uint32_t dst = stg + sl * PLANE_A + sw128((uint32_t)(row * 128 + x * 16));\
        cpa16(dst, g_Xs + (i64)sl * M_ * I_ + (i64)(by * BM + row) * I_           \
                       + (c) * 64 + x * 8);                                       \
    }                                                                             \
    _Pragma("unroll")                                                             \
    for (int v = 0; v < 12; v++) {                                                \
        int id = v * NTHR + tid;                                                  \
        int sl = id >> 10;                                                        \
        int idx = id & 1023;                                                      \
        int row = idx >> 3, x = idx & 7;                                          \
        uint32_t dst = stg + OFF_B + sl * PLANE_B                                 \
                     + sw128((uint32_t)(row * 128 + x * 16));                     \
        cpa16(dst, g_Ws + (i64)sl * H_ * I_ + (i64)(bx * BN + row) * I_           \
                       + (c) * 64 + x * 8);                                       \
    }                                                                             \
    CP_COMMIT();                                                                  \
} while (0)

// pair (i,j) -> accumulator set s=i+j; 8 m16n8 tile-mma per pair (m32 x n32)
#define PP(i, j, s) {                                                             \
    _Pragma("unroll")                                                             \
    for (int mt = 0; mt < 2; mt++)                                                \
        _Pragma("unroll")                                                         \
        for (int nt = 0; nt < 4; nt++)                                            \
            MMA(D[s][mt * 4 + nt], A[i][mt], Bt[j][nt]);                          \
}

#define COMPUTE_CHUNK(c) do {                                                     \
    uint32_t stg = sb + ((c) % NSTAGES) * STAGE;                                  \
    _Pragma("unroll")                                                             \
    for (int ks = 0; ks < 4; ks++) {                                              \
        uint32_t A[NSLICE][2][4];                                                 \
        _Pragma("unroll")                                                         \
        for (int sl = 0; sl < NSLICE; sl++) {                                     \
            _Pragma("unroll")                                                     \
            for (int mt = 0; mt < 2; mt++) {                                      \
                int row = wm * 32 + mt * 16 + ((q & 1) << 3) + l7;                \
                uint32_t ad = stg + sl * PLANE_A                                  \
                            + sw128((uint32_t)(row * 128 + ks * 32 + (q >> 1) * 16)); \
                ldsm4(A[sl][mt][0], A[sl][mt][1], A[sl][mt][2], A[sl][mt][3], ad);\
            }                                                                     \
        }                                                                         \
        uint32_t Bt[NSLICE][4][2];                                                \
        _Pragma("unroll")                                                         \
        for (int sl = 0; sl < NSLICE; sl++) {                                     \
            _Pragma("unroll")                                                     \
            for (int g = 0; g < 2; g++) {                                         \
                int n = wn * 32 + g * 16 + ((q & 1) << 3) + l7;                   \
                uint32_t bd = stg + OFF_B + sl * PLANE_B                          \
                            + sw128((uint32_t)(n * 128 + ks * 32 + (q >> 1) * 16)); \
                uint32_t r0, r1, r2, r3;                                          \
                ldsm4(r0, r1, r2, r3, bd);                                        \
                Bt[sl][2 * g][0] = r0;     Bt[sl][2 * g][1] = r2;                 \
                Bt[sl][2 * g + 1][0] = r1; Bt[sl][2 * g + 1][1] = r3;             \
            }                                                                     \
        }                                                                         \
        PP(0,0,0) PP(0,1,1) PP(0,2,2) PP(1,0,1) PP(1,1,2) PP(2,0,2)               \
    }                                                                             \
} while (0)

// Fold ONE accumulator set into P (shift = 9*(2-s)). Integer-exact.
#define FOLD_S(s, shift) do {                                                     \
    _Pragma("unroll")                                                             \
    for (int t = 0; t < 8; t++) {                                                 \
        _Pragma("unroll")                                                         \
        for (int e = 0; e < 4; e++) {                                             \
            P[t][e] += ((i64)(int)D[s][t][e] << (shift));                         \
            D[s][t][e] = 0.0f;                                                    \
        }                                                                         \
    }                                                                             \
} while (0)

    LOAD_CHUNK(0);
    LOAD_CHUNK(1);
    #pragma unroll 1
    for (int c = 0; c < NCHUNK; c++) {
        CP_WAIT1();            // chunk c resident (<=1 group pending)
        __syncthreads();       // all warps see chunk c; compute(c-1) done
        if (c + 2 < NCHUNK) LOAD_CHUNK(c + 2);   // overwrites stage (c-1): safe
        COMPUTE_CHUNK(c);
        FOLD_S(2, 0);                       // every chunk
        if ((c & 1) == 1) FOLD_S(1, 9);     // every 2 chunks
        if ((c & 3) == 3) FOLD_S(0, 18);    // every 4 chunks (NCHUNK%4==0)
    }

    // ---- epilogue: proj = P * 2^(ex+ew-34) + bias, one rounding ----
    #pragma unroll
    for (int mt = 0; mt < 2; mt++) {
        #pragma unroll
        for (int half = 0; half < 2; half++) {
            int m = by * BM + wm * 32 + mt * 16 + 8 * half + (lane >> 2);
            double sx = (double)g_sxf[m];            // 2^(ex-17)
            float* orow = proj + (size_t)m * H_ + bx * BN + wn * 32 + 2 * (lane & 3);
            #pragma unroll
            for (int nt = 0; nt < 4; nt++) {
                int t = mt * 4 + nt;
                float v[2];
                #pragma unroll
                for (int dj = 0; dj < 2; dj++) {
                    int h = bx * BN + wn * 32 + nt * 8 + 2 * (lane & 3) + dj;
                    int e = 2 * half + dj;
                    double sc = sx * (double)g_swf[h];   // 2^(ex+ew-34), exact
                    v[dj] = (float)((double)P[t][e] * sc + (double)bias[h]);
                }
                *(float2*)(orow + nt * 8) = make_float2(v[0], v[1]);
            }
        }
    }
#undef LOAD_CHUNK
#undef COMPUTE_CHUNK
#undef PP
#undef FOLD_S
}

// ---------------------------------------------------------------------------
// LIF scan: 4 consecutive h per thread, float4 IO (per-element math unchanged
// -> bit-identical). R16-measured: 63 us.
// ---------------------------------------------------------------------------
__global__ __launch_bounds__(256)
void lif_scan_kernel(const float* __restrict__ proj, float* __restrict__ out)
{
    int idx = blockIdx.x * blockDim.x + threadIdx.x;  // 0 .. B_*H_/4 - 1
    if (idx >= B_ * (H_ / 4)) return;
    int b  = idx / (H_ / 4);
    int h4 = idx % (H_ / 4);

    const float4* pin  = (const float4*)(proj + (size_t)b * T_ * H_) + h4;
    float4*       pout = (float4*)(out + (size_t)b * T_ * H_) + h4;

    float hs0 = 0.0f, hs1 = 0.0f, hs2 = 0.0f, hs3 = 0.0f;

    #pragma unroll 4
    for (int t = 0; t < T_; t++) {
        float4 p = pin[(size_t)t * (H_ / 4)];
        float4 sp;
        hs0 = __fadd_rn(__fmul_rn(0.9f, hs0), p.x);
        sp.x = (hs0 >= 1.0f) ? 1.0f : 0.0f;
        hs0 = __fmul_rn(hs0, __fsub_rn(1.0f, sp.x));
        hs1 = __fadd_rn(__fmul_rn(0.9f, hs1), p.y);
        sp.y = (hs1 >= 1.0f) ? 1.0f : 0.0f;
        hs1 = __fmul_rn(hs1, __fsub_rn(1.0f, sp.y));
        hs2 = __fadd_rn(__fmul_rn(0.9f, hs2), p.z);
        sp.z = (hs2 >= 1.0f) ? 1.0f : 0.0f;
        hs2 = __fmul_rn(hs2, __fsub_rn(1.0f, sp.z));
        hs3 = __fadd_rn(__fmul_rn(0.9f, hs3), p.w);
        sp.w = (hs3 >= 1.0f) ? 1.0f : 0.0f;
        hs3 = __fmul_rn(hs3, __fsub_rn(1.0f, sp.w));
        pout[(size_t)t * (H_ / 4)] = sp;
    }

    float4* pfin = (float4*)(out + (size_t)B_ * T_ * H_ + (size_t)b * H_) + h4;
    *pfin = make_float4(hs0, hs1, hs2, hs3);
}

// ---------------------------------------------------------------------------
extern "C" void kernel_launch(void* const* d_in, const int* in_sizes, int n_in,
                              void* d_out, int out_size)
{
    const float* X    = (const float*)d_in[0];
    const float* W    = (const float*)d_in[1];
    const float* bias = (const float*)d_in[2];
    float* out = (float*)d_out;

    unsigned short *Xs, *Ws;
    float *sxf, *swf, *proj;
    cudaGetSymbolAddress((void**)&Xs, g_Xs);
    cudaGetSymbolAddress((void**)&Ws, g_Ws);
    cudaGetSymbolAddress((void**)&sxf, g_sxf);
    cudaGetSymbolAddress((void**)&swf, g_swf);
    cudaGetSymbolAddress((void**)&proj, g_proj);

    cudaFuncSetAttribute(lif_gemm_hmma_kernel,
                         cudaFuncAttributeMaxDynamicSharedMemorySize, DSMEM);

    // signed base-512 digit splits (3 fp16 planes per operand) — FROZEN math
    split_kernel<<<M_, 256>>>(X, Xs, sxf, (i64)M_ * I_);
    split_kernel<<<H_, 256>>>(W, Ws, swf, (i64)H_ * I_);

    // fp16 HMMA GEMM, 6 pairs, immediate staggered folds (R15 placement)
    dim3 ggrid(NT, MT);   // (16, 400): bx fastest -> X tiles shared in L2
    lif_gemm_hmma_kernel<<<ggrid, NTHR, DSMEM>>>(bias, proj);

    // LIF scan (float4, bit-identical arithmetic)
    lif_scan_kernel<<<(B_ * (H_ / 4) + 255) / 256, 256>>>(proj, out);
}